// round 8
// baseline (speedup 1.0000x reference)
#include <cuda_runtime.h>
#include <cfloat>

// ---------------------------------------------------------------------------
// PillarMaxPooling: h = relu((x @ W) * bn_scale + bn_shift); segment_max -> M
//   k1: counting-bucket scatter of point IDS (int4-vectorized)
//   k2: warp-per-pillar, pipelined across pillars. Row gather uses 5 LANES PER
//       POINT (one LDG.64 covers 6 whole rows => wavefronts ~ lines, not
//       lanes); ids broadcast via shfl. Pair-packed SMEM double buffer,
//       f32x2 FMA mainloop at its pipe floor.
// ---------------------------------------------------------------------------

#define CAP      64
#define MAXM     262144
#define OVFCAP   65536
#define BN_EPS   1e-3f
#define K2_THREADS 256
#define K2_WARPS   8
#define CHUNK    18             // hot-path points per pillar chunk (9 pairs)
#define BUFW     192            // 9 pairs x 20 words + pad

__device__ int   d_count[MAXM];                 // zero-init, k2 re-zeroes
__device__ int   d_bucket[(size_t)MAXM * CAP];
__device__ int   d_ovflist[OVFCAP];
__device__ int   d_ovfcnt;                      // zero-init

typedef unsigned long long u64;

__device__ __forceinline__ u64 pk2(float x, float y) {
    u64 r; asm("mov.b64 %0, {%1, %2};" : "=l"(r) : "f"(x), "f"(y)); return r;
}
__device__ __forceinline__ void upk2(u64 v, float& x, float& y) {
    asm("mov.b64 {%0, %1}, %2;" : "=f"(x), "=f"(y) : "l"(v));
}
__device__ __forceinline__ u64 fma2(u64 a, u64 b, u64 c) {
    u64 d; asm("fma.rn.f32x2 %0, %1, %2, %3;" : "=l"(d) : "l"(a), "l"(b), "l"(c)); return d;
}
__device__ __forceinline__ u64 mul2(u64 a, u64 b) {
    u64 d; asm("mul.rn.f32x2 %0, %1, %2;" : "=l"(d) : "l"(a), "l"(b)); return d;
}

__device__ __forceinline__ void put_point(int i, int p) {
    int s = atomicAdd(&d_count[i], 1);
    if (s < CAP) {
        d_bucket[(unsigned)i * CAP + s] = p;
    } else {
        int o = atomicAdd(&d_ovfcnt, 1);
        if (o < OVFCAP) d_ovflist[o] = p;
        else atomicSub(&d_ovfcnt, 1);
    }
}

__global__ void k1_scatter(const int* __restrict__ idx, int P) {
    int t  = blockIdx.x * blockDim.x + threadIdx.x;
    int p0 = t * 4;
    if (p0 + 3 < P) {
        int4 v = *reinterpret_cast<const int4*>(idx + p0);
        put_point(v.x, p0);
        put_point(v.y, p0 + 1);
        put_point(v.z, p0 + 2);
        put_point(v.w, p0 + 3);
    } else {
        for (int p = p0; p < P; p++) put_point(idx[p], p);
    }
}

// Dot-product mainloop over a pair-packed SMEM buffer; accumulates max into mA/mB.
__device__ __forceinline__ void pair_mainloop(const float* buf, int m,
                                              const u64* wA, const u64* wB,
                                              float& mA, float& mB) {
    int  pairs = (m + 1) >> 1;
    bool odd   = (m & 1) != 0;
#pragma unroll 2
    for (int pr = 0; pr < pairs; pr++) {
        const ulonglong2* q = reinterpret_cast<const ulonglong2*>(buf + pr * 20);
        ulonglong2 q0 = q[0], q1 = q[1], q2 = q[2], q3 = q[3], q4 = q[4];
        u64 a = mul2(q0.x, wA[0]);
        u64 b = mul2(q0.x, wB[0]);
        a = fma2(q0.y, wA[1], a);  b = fma2(q0.y, wB[1], b);
        a = fma2(q1.x, wA[2], a);  b = fma2(q1.x, wB[2], b);
        a = fma2(q1.y, wA[3], a);  b = fma2(q1.y, wB[3], b);
        a = fma2(q2.x, wA[4], a);  b = fma2(q2.x, wB[4], b);
        a = fma2(q2.y, wA[5], a);  b = fma2(q2.y, wB[5], b);
        a = fma2(q3.x, wA[6], a);  b = fma2(q3.x, wB[6], b);
        a = fma2(q3.y, wA[7], a);  b = fma2(q3.y, wB[7], b);
        a = fma2(q4.x, wA[8], a);  b = fma2(q4.x, wB[8], b);
        a = fma2(q4.y, wA[9], a);  b = fma2(q4.y, wB[9], b);
        float xe, xo, ye, yo;
        upk2(a, xe, xo);
        upk2(b, ye, yo);
        if (odd && pr == pairs - 1) { xo = -FLT_MAX; yo = -FLT_MAX; }
        mA = fmaxf(fmaxf(mA, xe), xo);
        mB = fmaxf(fmaxf(mB, ye), yo);
    }
}

__global__ void __launch_bounds__(K2_THREADS)
k2_compute(const float* __restrict__ gf, const float* __restrict__ W,
           const float* __restrict__ gamma, const float* __restrict__ beta,
           const float* __restrict__ mean,  const float* __restrict__ var,
           const int* __restrict__ idx, float* __restrict__ out, int M) {
    __shared__ __align__(16) float sm[K2_WARPS][2][BUFW];   // 12 KB

    int lane = threadIdx.x & 31;
    int wloc = threadIdx.x >> 5;

    int gwarp = (blockIdx.x * K2_THREADS + threadIdx.x) >> 5;
    int nw    = (gridDim.x * K2_THREADS) >> 5;

    int  j5 = lane / 5;            // point-in-group 0..5 (lane<30)
    int  c5 = lane - 5 * j5;       // float2 chunk 0..4
    bool gl = lane < 30;

    int cA = 2 * lane, cB = 2 * lane + 1;
    float sA = gamma[cA] * rsqrtf(var[cA] + BN_EPS);
    float sB = gamma[cB] * rsqrtf(var[cB] + BN_EPS);
    float bA = beta[cA] - mean[cA] * sA;
    float bB = beta[cB] - mean[cB] * sB;

    u64 wA[10], wB[10];
#pragma unroll
    for (int k = 0; k < 10; k++) {
        float a = W[k * 64 + cA] * sA;
        float b = W[k * 64 + cB] * sB;
        wA[k] = pk2(a, a);
        wB[k] = pk2(b, b);
    }

    // ---- pipeline prologue -------------------------------------------------
    int i0 = gwarp, i1 = i0 + nw, i2 = i1 + nw, i3 = i2 + nw;

    int n0 = (i0 < M) ? d_count[i0] : 0;
    int m0 = n0 < CHUNK ? n0 : CHUNK;
    int id0 = 0;
    if (i0 < M && lane < m0) id0 = d_bucket[(unsigned)i0 * CAP + lane];
    float2 r[3];
#pragma unroll
    for (int g = 0; g < 3; g++) {
        int t   = 6 * g + j5;
        int pid = __shfl_sync(0xffffffffu, id0, t & 31);
        if (gl && t < m0)
            r[g] = *reinterpret_cast<const float2*>(gf + (unsigned)pid * 10u + 2 * c5);
    }
    int n1  = (i1 < M) ? d_count[i1] : 0;
    int id1 = 0;
    if (i1 < M && lane < (n1 < CHUNK ? n1 : CHUNK)) id1 = d_bucket[(unsigned)i1 * CAP + lane];
    int n2  = (i2 < M) ? d_count[i2] : 0;

    int cur = 0;
    // ---- pipelined main loop ------------------------------------------------
    while (i0 < M) {
        float* buf = sm[wloc][cur];

        // stage 1: deposit rows(i0) into pair-packed SMEM
#pragma unroll
        for (int g = 0; g < 3; g++) {
            int t = 6 * g + j5;
            if (gl && t < m0) {
                float* s = buf + (t >> 1) * 20 + (t & 1) + 4 * c5;
                s[0] = r[g].x;
                s[2] = r[g].y;
            }
        }
        // stage 2: issue rows(i1) LDGs (ids via shuffle from last iteration)
        int m1 = n1 < CHUNK ? n1 : CHUNK;
#pragma unroll
        for (int g = 0; g < 3; g++) {
            int t   = 6 * g + j5;
            int pid = __shfl_sync(0xffffffffu, id1, t & 31);
            if (gl && t < m1)
                r[g] = *reinterpret_cast<const float2*>(gf + (unsigned)pid * 10u + 2 * c5);
        }
        // stage 3: issue ids(i2) LDG
        int id2 = 0;
        if (i2 < M && lane < (n2 < CHUNK ? n2 : CHUNK)) id2 = d_bucket[(unsigned)i2 * CAP + lane];
        // stage 4: issue count(i3) LDG
        int n3 = (i3 < M) ? d_count[i3] : 0;

        __syncwarp();

        // compute pillar i0
        float mA = -FLT_MAX, mB = -FLT_MAX;
        pair_mainloop(buf, m0, wA, wB, mA, mB);

        // rare: extra chunks (CHUNK < n <= CAP), per-lane gather (not pipelined)
        if (n0 > CHUNK) {
            int nc = n0 < CAP ? n0 : CAP;
            for (int base = CHUNK; base < nc; base += CHUNK) {
                int m = nc - base; if (m > CHUNK) m = CHUNK;
                __syncwarp();
                if (lane < m) {
                    int pid = d_bucket[(unsigned)i0 * CAP + base + lane];
                    const float2* row = reinterpret_cast<const float2*>(gf + (unsigned)pid * 10u);
                    float2 v0 = row[0], v1 = row[1], v2 = row[2], v3 = row[3], v4 = row[4];
                    float vv[10] = {v0.x,v0.y,v1.x,v1.y,v2.x,v2.y,v3.x,v3.y,v4.x,v4.y};
                    float* s = buf + (lane >> 1) * 20 + (lane & 1);
#pragma unroll
                    for (int k = 0; k < 10; k++) s[2 * k] = vv[k];
                }
                __syncwarp();
                pair_mainloop(buf, m, wA, wB, mA, mB);
            }
        }
        // rare: overflow (n > CAP)
        if (n0 > CAP) {
            int V = d_ovfcnt; if (V > OVFCAP) V = OVFCAP;
            int mine = 0;
            for (int e = 0; e < V; e++) {
                int pid = d_ovflist[e];
                if (idx[pid] == i0) {
                    mine++;
                    u64 a = pk2(0.f, 0.f), b = a;
#pragma unroll
                    for (int k = 0; k < 10; k++) {
                        float f = gf[(unsigned)pid * 10u + k];
                        u64 ff = pk2(f, f);
                        a = fma2(ff, wA[k], a);
                        b = fma2(ff, wB[k], b);
                    }
                    float xa, t0, ya, t1;
                    upk2(a, xa, t0); upk2(b, ya, t1);
                    mA = fmaxf(mA, xa);
                    mB = fmaxf(mB, ya);
                }
            }
            if (lane == 0 && mine) atomicSub(&d_ovfcnt, mine);
        }

        if (lane == 0 && n0 > 0) d_count[i0] = 0;   // self-reset for graph replay

        float o0 = 0.0f, o1 = 0.0f;
        if (n0 > 0) {
            o0 = fmaxf(mA + bA, 0.0f);
            o1 = fmaxf(mB + bB, 0.0f);
        }
        *reinterpret_cast<float2*>(out + (unsigned)i0 * 64 + cA) = make_float2(o0, o1);

        // pipeline shift
        i0 = i1; n0 = n1; m0 = m1;
        i1 = i2; n1 = n2; id1 = id2;
        i2 = i3; n2 = n3;
        i3 += nw;
        cur ^= 1;
    }
}

extern "C" void kernel_launch(void* const* d_in, const int* in_sizes, int n_in,
                              void* d_out, int out_size) {
    const float* gf    = (const float*)d_in[0];
    const int*   idx   = (const int*)  d_in[1];
    const float* W     = (const float*)d_in[3];
    const float* gamma = (const float*)d_in[4];
    const float* beta  = (const float*)d_in[5];
    const float* mean  = (const float*)d_in[6];
    const float* var   = (const float*)d_in[7];
    float*       out   = (float*)d_out;

    int P = in_sizes[1];
    int M = out_size / 64;

    int g1 = (P / 4 + 255) / 256 + 1;
    k1_scatter<<<g1, 256>>>(idx, P);
    k2_compute<<<592, K2_THREADS>>>(gf, W, gamma, beta, mean, var, idx, out, M);
}

// round 9
// speedup vs baseline: 1.2121x; 1.2121x over previous
#include <cuda_runtime.h>
#include <cfloat>

// ---------------------------------------------------------------------------
// PillarMaxPooling: h = relu((x @ W) * bn_scale + bn_shift); segment_max -> M
//   k1: counting-bucket scatter of point IDS (int4-vectorized)
//   k2: warp-per-pillar, pipelined across pillars. Row gather uses 5 lanes per
//       point (6 points per LDG.64 pass -> wavefronts ~ lines, not lanes) with
//       ids relayed through double-buffered SMEM (no shfl on the critical
//       path). Pair-packed SMEM buffer, f32x2 FMA mainloop at its pipe floor.
// ---------------------------------------------------------------------------

#define CAP      64
#define MAXM     262144
#define OVFCAP   65536
#define BN_EPS   1e-3f
#define K2_THREADS 256
#define K2_WARPS   8
#define CHUNK    24             // hot-path points per pillar chunk (12 pairs)
#define BUFW     240            // 12 pairs x 20 words

__device__ int   d_count[MAXM];                 // zero-init, k2 re-zeroes
__device__ int   d_bucket[(size_t)MAXM * CAP];
__device__ int   d_ovflist[OVFCAP];
__device__ int   d_ovfcnt;                      // zero-init

typedef unsigned long long u64;

__device__ __forceinline__ u64 pk2(float x, float y) {
    u64 r; asm("mov.b64 %0, {%1, %2};" : "=l"(r) : "f"(x), "f"(y)); return r;
}
__device__ __forceinline__ void upk2(u64 v, float& x, float& y) {
    asm("mov.b64 {%0, %1}, %2;" : "=f"(x), "=f"(y) : "l"(v));
}
__device__ __forceinline__ u64 fma2(u64 a, u64 b, u64 c) {
    u64 d; asm("fma.rn.f32x2 %0, %1, %2, %3;" : "=l"(d) : "l"(a), "l"(b), "l"(c)); return d;
}
__device__ __forceinline__ u64 mul2(u64 a, u64 b) {
    u64 d; asm("mul.rn.f32x2 %0, %1, %2;" : "=l"(d) : "l"(a), "l"(b)); return d;
}

__device__ __forceinline__ void put_point(int i, int p) {
    int s = atomicAdd(&d_count[i], 1);
    if (s < CAP) {
        d_bucket[(unsigned)i * CAP + s] = p;
    } else {
        int o = atomicAdd(&d_ovfcnt, 1);
        if (o < OVFCAP) d_ovflist[o] = p;
        else atomicSub(&d_ovfcnt, 1);
    }
}

__global__ void k1_scatter(const int* __restrict__ idx, int P) {
    int t  = blockIdx.x * blockDim.x + threadIdx.x;
    int p0 = t * 4;
    if (p0 + 3 < P) {
        int4 v = *reinterpret_cast<const int4*>(idx + p0);
        put_point(v.x, p0);
        put_point(v.y, p0 + 1);
        put_point(v.z, p0 + 2);
        put_point(v.w, p0 + 3);
    } else {
        for (int p = p0; p < P; p++) put_point(idx[p], p);
    }
}

// Dot-product mainloop over a pair-packed SMEM buffer; accumulates max into mA/mB.
__device__ __forceinline__ void pair_mainloop(const float* buf, int m,
                                              const u64* wA, const u64* wB,
                                              float& mA, float& mB) {
    int  pairs = (m + 1) >> 1;
    bool odd   = (m & 1) != 0;
#pragma unroll 2
    for (int pr = 0; pr < pairs; pr++) {
        const ulonglong2* q = reinterpret_cast<const ulonglong2*>(buf + pr * 20);
        ulonglong2 q0 = q[0], q1 = q[1], q2 = q[2], q3 = q[3], q4 = q[4];
        u64 a = mul2(q0.x, wA[0]);
        u64 b = mul2(q0.x, wB[0]);
        a = fma2(q0.y, wA[1], a);  b = fma2(q0.y, wB[1], b);
        a = fma2(q1.x, wA[2], a);  b = fma2(q1.x, wB[2], b);
        a = fma2(q1.y, wA[3], a);  b = fma2(q1.y, wB[3], b);
        a = fma2(q2.x, wA[4], a);  b = fma2(q2.x, wB[4], b);
        a = fma2(q2.y, wA[5], a);  b = fma2(q2.y, wB[5], b);
        a = fma2(q3.x, wA[6], a);  b = fma2(q3.x, wB[6], b);
        a = fma2(q3.y, wA[7], a);  b = fma2(q3.y, wB[7], b);
        a = fma2(q4.x, wA[8], a);  b = fma2(q4.x, wB[8], b);
        a = fma2(q4.y, wA[9], a);  b = fma2(q4.y, wB[9], b);
        float xe, xo, ye, yo;
        upk2(a, xe, xo);
        upk2(b, ye, yo);
        if (odd && pr == pairs - 1) { xo = -FLT_MAX; yo = -FLT_MAX; }
        mA = fmaxf(fmaxf(mA, xe), xo);
        mB = fmaxf(fmaxf(mB, ye), yo);
    }
}

__global__ void __launch_bounds__(K2_THREADS)
k2_compute(const float* __restrict__ gf, const float* __restrict__ W,
           const float* __restrict__ gamma, const float* __restrict__ beta,
           const float* __restrict__ mean,  const float* __restrict__ var,
           const int* __restrict__ idx, float* __restrict__ out, int M) {
    __shared__ __align__(16) float sm[K2_WARPS][2][BUFW];   // 15.4 KB
    __shared__ int sid[K2_WARPS][2][CHUNK];                 // 1.5 KB

    int lane = threadIdx.x & 31;
    int wloc = threadIdx.x >> 5;

    int gwarp = (blockIdx.x * K2_THREADS + threadIdx.x) >> 5;
    int nw    = (gridDim.x * K2_THREADS) >> 5;

    int  j5 = lane / 5;            // point-in-group 0..5 (lane<30)
    int  c5 = lane - 5 * j5;       // float2 chunk 0..4
    bool gl = lane < 30;

    int cA = 2 * lane, cB = 2 * lane + 1;
    float sA = gamma[cA] * rsqrtf(var[cA] + BN_EPS);
    float sB = gamma[cB] * rsqrtf(var[cB] + BN_EPS);
    float bA = beta[cA] - mean[cA] * sA;
    float bB = beta[cB] - mean[cB] * sB;

    u64 wA[10], wB[10];
#pragma unroll
    for (int k = 0; k < 10; k++) {
        float a = W[k * 64 + cA] * sA;
        float b = W[k * 64 + cB] * sB;
        wA[k] = pk2(a, a);
        wB[k] = pk2(b, b);
    }

    // ---- pipeline prologue -------------------------------------------------
    int i0 = gwarp, i1 = i0 + nw, i2 = i1 + nw, i3 = i2 + nw;

    int n0 = (i0 < M) ? d_count[i0] : 0;
    int m0 = n0 < CHUNK ? n0 : CHUNK;
    if (lane < m0) sid[wloc][0][lane] = d_bucket[(unsigned)i0 * CAP + lane];
    __syncwarp();
    float2 r[4];
#pragma unroll
    for (int g = 0; g < 4; g++) {
        int t = 6 * g + j5;
        if (gl && t < m0) {
            int pid = sid[wloc][0][t];
            r[g] = *reinterpret_cast<const float2*>(gf + (unsigned)pid * 10u + 2 * c5);
        }
    }
    int n1  = (i1 < M) ? d_count[i1] : 0;
    int id1 = 0;
    if (i1 < M && lane < (n1 < CHUNK ? n1 : CHUNK)) id1 = d_bucket[(unsigned)i1 * CAP + lane];
    int n2  = (i2 < M) ? d_count[i2] : 0;
    __syncwarp();   // protect prologue sid reads before loop re-writes slot 0

    int cur = 0;
    // ---- pipelined main loop ------------------------------------------------
    while (i0 < M) {
        float* buf = sm[wloc][cur];
        int*   ids = sid[wloc][cur];

        // (1) stash ids(i1) (in registers since last iteration) for the gather
        if (lane < CHUNK) ids[lane] = id1;
        // (2) deposit rows(i0) into pair-packed SMEM
#pragma unroll
        for (int g = 0; g < 4; g++) {
            int t = 6 * g + j5;
            if (gl && t < m0) {
                float* s = buf + (t >> 1) * 20 + (t & 1) + 4 * c5;
                s[0] = r[g].x;
                s[2] = r[g].y;
            }
        }
        __syncwarp();

        // (3) gather rows(i1): 6 points per LDG pass, ids via SMEM broadcast
        int m1 = n1 < CHUNK ? n1 : CHUNK;
#pragma unroll
        for (int g = 0; g < 4; g++) {
            int t = 6 * g + j5;
            if (gl && t < m1) {
                int pid = ids[t];
                r[g] = *reinterpret_cast<const float2*>(gf + (unsigned)pid * 10u + 2 * c5);
            }
        }
        // (4) ids(i2) -> registers
        int id2 = 0;
        if (i2 < M && lane < (n2 < CHUNK ? n2 : CHUNK)) id2 = d_bucket[(unsigned)i2 * CAP + lane];
        // (5) count(i3)
        int n3 = (i3 < M) ? d_count[i3] : 0;

        // (6) compute pillar i0
        float mA = -FLT_MAX, mB = -FLT_MAX;
        pair_mainloop(buf, m0, wA, wB, mA, mB);

        // rare: extra chunks (CHUNK < n <= CAP), per-lane gather (not pipelined)
        if (n0 > CHUNK) {
            int nc = n0 < CAP ? n0 : CAP;
            for (int base = CHUNK; base < nc; base += CHUNK) {
                int m = nc - base; if (m > CHUNK) m = CHUNK;
                __syncwarp();
                if (lane < m) {
                    int pid = d_bucket[(unsigned)i0 * CAP + base + lane];
                    const float2* row = reinterpret_cast<const float2*>(gf + (unsigned)pid * 10u);
                    float2 v0 = row[0], v1 = row[1], v2 = row[2], v3 = row[3], v4 = row[4];
                    float vv[10] = {v0.x,v0.y,v1.x,v1.y,v2.x,v2.y,v3.x,v3.y,v4.x,v4.y};
                    float* s = buf + (lane >> 1) * 20 + (lane & 1);
#pragma unroll
                    for (int k = 0; k < 10; k++) s[2 * k] = vv[k];
                }
                __syncwarp();
                pair_mainloop(buf, m, wA, wB, mA, mB);
            }
        }
        // rare: overflow (n > CAP)
        if (n0 > CAP) {
            int V = d_ovfcnt; if (V > OVFCAP) V = OVFCAP;
            int mine = 0;
            for (int e = 0; e < V; e++) {
                int pid = d_ovflist[e];
                if (idx[pid] == i0) {
                    mine++;
                    u64 a = pk2(0.f, 0.f), b = a;
#pragma unroll
                    for (int k = 0; k < 10; k++) {
                        float f = gf[(unsigned)pid * 10u + k];
                        u64 ff = pk2(f, f);
                        a = fma2(ff, wA[k], a);
                        b = fma2(ff, wB[k], b);
                    }
                    float xa, t0, ya, t1;
                    upk2(a, xa, t0); upk2(b, ya, t1);
                    mA = fmaxf(mA, xa);
                    mB = fmaxf(mB, ya);
                }
            }
            if (lane == 0 && mine) atomicSub(&d_ovfcnt, mine);
        }

        if (lane == 0 && n0 > 0) d_count[i0] = 0;   // self-reset for graph replay

        float o0 = 0.0f, o1 = 0.0f;
        if (n0 > 0) {
            o0 = fmaxf(mA + bA, 0.0f);
            o1 = fmaxf(mB + bB, 0.0f);
        }
        *reinterpret_cast<float2*>(out + (unsigned)i0 * 64 + cA) = make_float2(o0, o1);

        // pipeline shift
        i0 = i1; n0 = n1; m0 = m1;
        i1 = i2; n1 = n2; id1 = id2;
        i2 = i3; n2 = n3;
        i3 += nw;
        cur ^= 1;
    }
}

extern "C" void kernel_launch(void* const* d_in, const int* in_sizes, int n_in,
                              void* d_out, int out_size) {
    const float* gf    = (const float*)d_in[0];
    const int*   idx   = (const int*)  d_in[1];
    const float* W     = (const float*)d_in[3];
    const float* gamma = (const float*)d_in[4];
    const float* beta  = (const float*)d_in[5];
    const float* mean  = (const float*)d_in[6];
    const float* var   = (const float*)d_in[7];
    float*       out   = (float*)d_out;

    int P = in_sizes[1];
    int M = out_size / 64;

    int g1 = (P / 4 + 255) / 256 + 1;
    k1_scatter<<<g1, 256>>>(idx, P);
    k2_compute<<<592, K2_THREADS>>>(gf, W, gamma, beta, mean, var, idx, out, M);
}

// round 10
// speedup vs baseline: 1.3645x; 1.1258x over previous
#include <cuda_runtime.h>
#include <cfloat>

// ---------------------------------------------------------------------------
// PillarMaxPooling: h = relu((x @ W) * bn_scale + bn_shift); segment_max -> M
//   k1: counting-bucket scatter of point IDS (int4-vectorized)
//   k2: warp-per-pillar, 3-stage SOFTWARE PIPELINE across pillars (R7 design).
//       Grid sized to EXACTLY one resident wave (regs=80 -> 3 CTA/SM -> 444).
// ---------------------------------------------------------------------------

#define CAP      64
#define MAXM     262144
#define OVFCAP   65536
#define BN_EPS   1e-3f
#define K2_THREADS 256
#define K2_WARPS   8
#define K2_GRID  444            // 3 CTAs/SM x 148 SMs: exactly one wave
#define BUFW     320            // 16 pairs x 20 words (32 points)

__device__ int   d_count[MAXM];                 // zero-init, k2 re-zeroes
__device__ int   d_bucket[(size_t)MAXM * CAP];
__device__ int   d_ovflist[OVFCAP];
__device__ int   d_ovfcnt;                      // zero-init

typedef unsigned long long u64;

__device__ __forceinline__ u64 pk2(float x, float y) {
    u64 r; asm("mov.b64 %0, {%1, %2};" : "=l"(r) : "f"(x), "f"(y)); return r;
}
__device__ __forceinline__ void upk2(u64 v, float& x, float& y) {
    asm("mov.b64 {%0, %1}, %2;" : "=f"(x), "=f"(y) : "l"(v));
}
__device__ __forceinline__ u64 fma2(u64 a, u64 b, u64 c) {
    u64 d; asm("fma.rn.f32x2 %0, %1, %2, %3;" : "=l"(d) : "l"(a), "l"(b), "l"(c)); return d;
}
__device__ __forceinline__ u64 mul2(u64 a, u64 b) {
    u64 d; asm("mul.rn.f32x2 %0, %1, %2;" : "=l"(d) : "l"(a), "l"(b)); return d;
}

__device__ __forceinline__ void put_point(int i, int p) {
    int s = atomicAdd(&d_count[i], 1);
    if (s < CAP) {
        d_bucket[(unsigned)i * CAP + s] = p;
    } else {
        int o = atomicAdd(&d_ovfcnt, 1);
        if (o < OVFCAP) d_ovflist[o] = p;
        else atomicSub(&d_ovfcnt, 1);
    }
}

__global__ void k1_scatter(const int* __restrict__ idx, int P) {
    int t  = blockIdx.x * blockDim.x + threadIdx.x;
    int p0 = t * 4;
    if (p0 + 3 < P) {
        int4 v = *reinterpret_cast<const int4*>(idx + p0);
        put_point(v.x, p0);
        put_point(v.y, p0 + 1);
        put_point(v.z, p0 + 2);
        put_point(v.w, p0 + 3);
    } else {
        for (int p = p0; p < P; p++) put_point(idx[p], p);
    }
}

// Dot-product mainloop over a pair-packed SMEM buffer; accumulates max into mA/mB.
__device__ __forceinline__ void pair_mainloop(const float* buf, int m,
                                              const u64* wA, const u64* wB,
                                              float& mA, float& mB) {
    int  pairs = (m + 1) >> 1;
    bool odd   = (m & 1) != 0;
#pragma unroll 2
    for (int pr = 0; pr < pairs; pr++) {
        const ulonglong2* q = reinterpret_cast<const ulonglong2*>(buf + pr * 20);
        ulonglong2 q0 = q[0], q1 = q[1], q2 = q[2], q3 = q[3], q4 = q[4];
        u64 a = mul2(q0.x, wA[0]);
        u64 b = mul2(q0.x, wB[0]);
        a = fma2(q0.y, wA[1], a);  b = fma2(q0.y, wB[1], b);
        a = fma2(q1.x, wA[2], a);  b = fma2(q1.x, wB[2], b);
        a = fma2(q1.y, wA[3], a);  b = fma2(q1.y, wB[3], b);
        a = fma2(q2.x, wA[4], a);  b = fma2(q2.x, wB[4], b);
        a = fma2(q2.y, wA[5], a);  b = fma2(q2.y, wB[5], b);
        a = fma2(q3.x, wA[6], a);  b = fma2(q3.x, wB[6], b);
        a = fma2(q3.y, wA[7], a);  b = fma2(q3.y, wB[7], b);
        a = fma2(q4.x, wA[8], a);  b = fma2(q4.x, wB[8], b);
        a = fma2(q4.y, wA[9], a);  b = fma2(q4.y, wB[9], b);
        float xe, xo, ye, yo;
        upk2(a, xe, xo);
        upk2(b, ye, yo);
        if (odd && pr == pairs - 1) { xo = -FLT_MAX; yo = -FLT_MAX; }
        mA = fmaxf(fmaxf(mA, xe), xo);
        mB = fmaxf(fmaxf(mB, ye), yo);
    }
}

__global__ void __launch_bounds__(K2_THREADS)
k2_compute(const float* __restrict__ gf, const float* __restrict__ W,
           const float* __restrict__ gamma, const float* __restrict__ beta,
           const float* __restrict__ mean,  const float* __restrict__ var,
           const int* __restrict__ idx, float* __restrict__ out, int M) {
    __shared__ __align__(16) float sm[K2_WARPS][2][BUFW];   // 20 KB

    int lane = threadIdx.x & 31;
    int wloc = threadIdx.x >> 5;

    int gwarp = (blockIdx.x * K2_THREADS + threadIdx.x) >> 5;
    int nw    = (gridDim.x * K2_THREADS) >> 5;

    int cA = 2 * lane, cB = 2 * lane + 1;
    float sA = gamma[cA] * rsqrtf(var[cA] + BN_EPS);
    float sB = gamma[cB] * rsqrtf(var[cB] + BN_EPS);
    float bA = beta[cA] - mean[cA] * sA;
    float bB = beta[cB] - mean[cB] * sB;

    u64 wA[10], wB[10];
#pragma unroll
    for (int k = 0; k < 10; k++) {
        float a = W[k * 64 + cA] * sA;
        float b = W[k * 64 + cB] * sB;
        wA[k] = pk2(a, a);
        wB[k] = pk2(b, b);
    }

    // ---- pipeline prologue -------------------------------------------------
    int i0 = gwarp, i1 = i0 + nw, i2 = i1 + nw, i3 = i2 + nw;

    int n0 = (i0 < M) ? d_count[i0] : 0;
    int m0 = n0 < 32 ? n0 : 32;
    float r[10];
    if (i0 < M && lane < m0) {
        int pid = d_bucket[(unsigned)i0 * CAP + lane];
        const float2* row = reinterpret_cast<const float2*>(gf + (unsigned)pid * 10u);
        float2 v0 = row[0], v1 = row[1], v2 = row[2], v3 = row[3], v4 = row[4];
        r[0]=v0.x; r[1]=v0.y; r[2]=v1.x; r[3]=v1.y; r[4]=v2.x;
        r[5]=v2.y; r[6]=v3.x; r[7]=v3.y; r[8]=v4.x; r[9]=v4.y;
    }
    int n1  = (i1 < M) ? d_count[i1] : 0;
    int id1 = 0;
    if (i1 < M && lane < (n1 < 32 ? n1 : 32)) id1 = d_bucket[(unsigned)i1 * CAP + lane];
    int n2  = (i2 < M) ? d_count[i2] : 0;

    int cur = 0;
    // ---- pipelined main loop ------------------------------------------------
    while (i0 < M) {
        float* buf = sm[wloc][cur];

        // stage 1: deposit rows(i0) into SMEM (pair-packed, <= 16 pairs)
        if (lane < m0) {
            float* s = buf + (lane >> 1) * 20 + (lane & 1);
#pragma unroll
            for (int k = 0; k < 10; k++) s[2 * k] = r[k];
        }
        // stage 2: issue rows(i1) LDGs (uses id1 from last iteration)
        int m1 = n1 < 32 ? n1 : 32;
        if (i1 < M && lane < m1) {
            const float2* row = reinterpret_cast<const float2*>(gf + (unsigned)id1 * 10u);
            float2 v0 = row[0], v1 = row[1], v2 = row[2], v3 = row[3], v4 = row[4];
            r[0]=v0.x; r[1]=v0.y; r[2]=v1.x; r[3]=v1.y; r[4]=v2.x;
            r[5]=v2.y; r[6]=v3.x; r[7]=v3.y; r[8]=v4.x; r[9]=v4.y;
        }
        // stage 3: issue ids(i2) LDG (uses n2 from last iteration)
        int id2 = 0;
        if (i2 < M && lane < (n2 < 32 ? n2 : 32)) id2 = d_bucket[(unsigned)i2 * CAP + lane];
        // stage 4: issue count(i3) LDG
        int n3 = (i3 < M) ? d_count[i3] : 0;

        __syncwarp();

        // compute pillar i0
        float mA = -FLT_MAX, mB = -FLT_MAX;
        pair_mainloop(buf, m0, wA, wB, mA, mB);

        // rare: extra chunks (32 < n <= CAP)
        if (n0 > 32) {
            int nc = n0 < CAP ? n0 : CAP;
            for (int base = 32; base < nc; base += 32) {
                int m = nc - base; if (m > 32) m = 32;
                __syncwarp();
                if (lane < m) {
                    int pid = d_bucket[(unsigned)i0 * CAP + base + lane];
                    const float2* row = reinterpret_cast<const float2*>(gf + (unsigned)pid * 10u);
                    float2 v0 = row[0], v1 = row[1], v2 = row[2], v3 = row[3], v4 = row[4];
                    float vv[10] = {v0.x,v0.y,v1.x,v1.y,v2.x,v2.y,v3.x,v3.y,v4.x,v4.y};
                    float* s = buf + (lane >> 1) * 20 + (lane & 1);
#pragma unroll
                    for (int k = 0; k < 10; k++) s[2 * k] = vv[k];
                }
                __syncwarp();
                pair_mainloop(buf, m, wA, wB, mA, mB);
            }
        }
        // rare: overflow (n > CAP)
        if (n0 > CAP) {
            int V = d_ovfcnt; if (V > OVFCAP) V = OVFCAP;
            int mine = 0;
            for (int e = 0; e < V; e++) {
                int pid = d_ovflist[e];
                if (idx[pid] == i0) {
                    mine++;
                    u64 a = pk2(0.f, 0.f), b = a;
#pragma unroll
                    for (int k = 0; k < 10; k++) {
                        float f = gf[(unsigned)pid * 10u + k];
                        u64 ff = pk2(f, f);
                        a = fma2(ff, wA[k], a);
                        b = fma2(ff, wB[k], b);
                    }
                    float xa, t0, ya, t1;
                    upk2(a, xa, t0); upk2(b, ya, t1);
                    mA = fmaxf(mA, xa);
                    mB = fmaxf(mB, ya);
                }
            }
            if (lane == 0 && mine) atomicSub(&d_ovfcnt, mine);
        }

        if (lane == 0 && n0 > 0) d_count[i0] = 0;   // self-reset for graph replay

        float o0 = 0.0f, o1 = 0.0f;
        if (n0 > 0) {
            o0 = fmaxf(mA + bA, 0.0f);
            o1 = fmaxf(mB + bB, 0.0f);
        }
        *reinterpret_cast<float2*>(out + (unsigned)i0 * 64 + cA) = make_float2(o0, o1);

        // pipeline shift
        i0 = i1; n0 = n1; m0 = m1;
        i1 = i2; n1 = n2; id1 = id2;
        i2 = i3; n2 = n3;
        i3 += nw;
        cur ^= 1;
    }
}

extern "C" void kernel_launch(void* const* d_in, const int* in_sizes, int n_in,
                              void* d_out, int out_size) {
    const float* gf    = (const float*)d_in[0];
    const int*   idx   = (const int*)  d_in[1];
    const float* W     = (const float*)d_in[3];
    const float* gamma = (const float*)d_in[4];
    const float* beta  = (const float*)d_in[5];
    const float* mean  = (const float*)d_in[6];
    const float* var   = (const float*)d_in[7];
    float*       out   = (float*)d_out;

    int P = in_sizes[1];
    int M = out_size / 64;

    int g1 = (P / 4 + 255) / 256 + 1;
    k1_scatter<<<g1, 256>>>(idx, P);
    k2_compute<<<K2_GRID, K2_THREADS>>>(gf, W, gamma, beta, mean, var, idx, out, M);
}